// round 8
// baseline (speedup 1.0000x reference)
#include <cuda_runtime.h>

// Cross_Attention_32469952757796 — linear-attention decomposition, R8 build.
#define NN      16384            // H*W
#define BHEADS  64               // B * HEADS
#define TILE2   1024             // N-chunk for ctx kernel
#define NCHUNK  (NN / TILE2)     // 16
#define CTX_SMEM (16 * TILE2 * sizeof(float))   // 64 KB dynamic

// Scratch (allocation-free rule: __device__ globals). Fully overwritten each run.
__device__ float g_part[BHEADS][NCHUNK][256];  // per-chunk ctx partials [k*16+v]
__device__ float g_rsp[BHEADS][NCHUNK][16];    // per-chunk rowsum partials

typedef unsigned long long ull;

// ---- packed f32x2 helpers (sm_100a) --------------------------------------
__device__ __forceinline__ ull pack2(float lo, float hi) {
    ull d; asm("mov.b64 %0, {%1, %2};" : "=l"(d) : "f"(lo), "f"(hi)); return d;
}
__device__ __forceinline__ void unpack2(ull v, float& a, float& b) {
    asm("mov.b64 {%0, %1}, %2;" : "=f"(a), "=f"(b) : "l"(v));
}
__device__ __forceinline__ void fma2(ull& d, ull a, ull b) {
    asm("fma.rn.f32x2 %0, %1, %2, %0;" : "+l"(d) : "l"(a), "l"(b));
}
__device__ __forceinline__ ull add2(ull a, ull b) {
    ull d; asm("add.rn.f32x2 %0, %1, %2;" : "=l"(d) : "l"(a), "l"(b)); return d;
}
__device__ __forceinline__ ull mul2(ull a, ull b) {
    ull d; asm("mul.rn.f32x2 %0, %1, %2;" : "=l"(d) : "l"(a), "l"(b)); return d;
}

// ---------------------------------------------------------------------------
// Kernel 1: per-chunk unnormalized context + row sums (no atomics):
//   g_part[bh][ch][k][v] = sum_{n in ch} exp(x2[k,n]) * x1[v,n]
//   g_rsp[bh][ch][k]     = sum_{n in ch} exp(x2[k,n])
// grid = (NCHUNK, 64), 256 threads (8 warps).
// Warp tiling: warp w -> k-group g=w>>1 (4 rows), v-group h=w&1 (8 rows).
// Halves smem v-row traffic vs 2k x 16v; x2 rows read by 2 warps (L2-hit).
// ---------------------------------------------------------------------------
__global__ __launch_bounds__(256) void ctx_kernel(const float* __restrict__ x1,
                                                  const float* __restrict__ x2) {
    extern __shared__ float smv[];   // [16][TILE2]

    const int bh    = blockIdx.y;
    const int chunk = blockIdx.x;
    const int n0    = chunk * TILE2;
    const int tid   = threadIdx.x;

    // cooperative float4 load of x1 tile [16][TILE2]
    const float* vb = x1 + (size_t)bh * 16 * NN + n0;
    for (int idx = tid; idx < 16 * (TILE2 / 4); idx += 256) {
        int c  = idx / (TILE2 / 4);
        int j4 = idx % (TILE2 / 4);
        ((float4*)smv)[c * (TILE2 / 4) + j4] =
            ((const float4*)(vb + (size_t)c * NN))[j4];
    }
    __syncthreads();

    const int w    = tid >> 5;
    const int lane = tid & 31;
    const int g    = w >> 1;          // k-group: rows k0..k0+3
    const int h    = w & 1;           // v-group: rows v0..v0+7
    const int k0   = g * 4;
    const int v0   = h * 8;

    const float* qr0 = x2 + (size_t)(bh * 16 + k0) * NN + n0;
    const float* qr1 = qr0 + NN;
    const float* qr2 = qr1 + NN;
    const float* qr3 = qr2 + NN;

    ull acc[4][8];
    #pragma unroll
    for (int i = 0; i < 4; i++)
        #pragma unroll
        for (int v = 0; v < 8; v++) acc[i][v] = 0ull;
    ull s[4] = {0ull, 0ull, 0ull, 0ull};

    #pragma unroll
    for (int jt = 0; jt < TILE2; jt += 128) {
        const int j = jt + lane * 4;
        float4 a0 = *(const float4*)(qr0 + j);
        float4 a1 = *(const float4*)(qr1 + j);
        float4 a2 = *(const float4*)(qr2 + j);
        float4 a3 = *(const float4*)(qr3 + j);
        ull p01[4], p23[4];
        p01[0] = pack2(__expf(a0.x), __expf(a0.y));
        p23[0] = pack2(__expf(a0.z), __expf(a0.w));
        p01[1] = pack2(__expf(a1.x), __expf(a1.y));
        p23[1] = pack2(__expf(a1.z), __expf(a1.w));
        p01[2] = pack2(__expf(a2.x), __expf(a2.y));
        p23[2] = pack2(__expf(a2.z), __expf(a2.w));
        p01[3] = pack2(__expf(a3.x), __expf(a3.y));
        p23[3] = pack2(__expf(a3.z), __expf(a3.w));
        #pragma unroll
        for (int i = 0; i < 4; i++) s[i] = add2(s[i], add2(p01[i], p23[i]));

        #pragma unroll
        for (int v = 0; v < 8; v++) {
            float4 vv = *(const float4*)&smv[(v0 + v) * TILE2 + j];
            ull v01 = pack2(vv.x, vv.y);
            ull v23 = pack2(vv.z, vv.w);
            #pragma unroll
            for (int i = 0; i < 4; i++) {
                fma2(acc[i][v], p01[i], v01);
                fma2(acc[i][v], p23[i], v23);
            }
        }
    }

    // scalarize packed accumulators, then warp butterfly (36 scalars)
    float sc[36];
    #pragma unroll
    for (int i = 0; i < 4; i++)
        #pragma unroll
        for (int v = 0; v < 8; v++) {
            float a, b;
            unpack2(acc[i][v], a, b);
            sc[i * 8 + v] = a + b;
        }
    #pragma unroll
    for (int i = 0; i < 4; i++) {
        float a, b; unpack2(s[i], a, b);
        sc[32 + i] = a + b;
    }

    #pragma unroll
    for (int off = 16; off > 0; off >>= 1) {
        #pragma unroll
        for (int i = 0; i < 36; i++)
            sc[i] += __shfl_xor_sync(0xffffffffu, sc[i], off);
    }

    if (lane == 0) {
        float* dst = &g_part[bh][chunk][0];
        #pragma unroll
        for (int i = 0; i < 4; i++)
            #pragma unroll
            for (int v = 0; v < 8; v++)
                dst[(k0 + i) * 16 + v0 + v] = sc[i * 8 + v];
        if (h == 0) {
            #pragma unroll
            for (int i = 0; i < 4; i++)
                g_rsp[bh][chunk][k0 + i] = sc[32 + i];
        }
    }
}

// ---------------------------------------------------------------------------
// Kernel 2: out[v,n] = sum_k (ctx[k,v]/S_k) * softmax_k(x2[:,n])[k]
// grid = (32, 64), 256 threads; each thread owns ONE float2 column pair.
// k-OUTER form: 16 packed accumulators a[v] in registers; per k one LDG.64,
// 2 exp, 4 broadcast LDS.128 (ctx row), 16 fma2. Softmax sum folded in.
// LDS per thread: 64 (was 128); no q[] array (regs ~50 -> 4 CTA/SM).
// ---------------------------------------------------------------------------
__global__ __launch_bounds__(256, 4) void out_kernel(const float* __restrict__ x2,
                                                     float* __restrict__ out) {
    __shared__ ull   sctx2[256];   // [k][v], each = {c,c}
    __shared__ float srs[16];

    const int bh  = blockIdx.y;
    const int tid = threadIdx.x;

    if (tid < 16) {
        float s = 0.f;
        #pragma unroll
        for (int ch = 0; ch < NCHUNK; ch++) s += g_rsp[bh][ch][tid];
        srs[tid] = 1.f / s;
    }
    float cv = 0.f;
    #pragma unroll
    for (int ch = 0; ch < NCHUNK; ch++) cv += g_part[bh][ch][tid];
    __syncthreads();
    {
        const int k = tid >> 4;
        const float c = cv * srs[k];
        sctx2[tid] = pack2(c, c);
    }
    __syncthreads();

    const size_t base = (size_t)bh * 16 * NN;
    const int n = blockIdx.x * 512 + tid * 2;
    const float* px = x2 + base + n;

    ull a[16];
    #pragma unroll
    for (int v = 0; v < 16; v++) a[v] = 0ull;
    ull s01 = 0ull;

    #pragma unroll 4
    for (int k = 0; k < 16; k++) {
        float2 t = *(const float2*)(px + (size_t)k * NN);
        ull qk = pack2(__expf(t.x), __expf(t.y));
        s01 = add2(s01, qk);
        const ull* crow = &sctx2[k * 16];
        #pragma unroll
        for (int v4 = 0; v4 < 4; v4++) {
            longlong2 cA = *(const longlong2*)(crow + v4 * 4);
            longlong2 cB = *(const longlong2*)(crow + v4 * 4 + 2);
            fma2(a[v4 * 4 + 0], qk, (ull)cA.x);
            fma2(a[v4 * 4 + 1], qk, (ull)cA.y);
            fma2(a[v4 * 4 + 2], qk, (ull)cB.x);
            fma2(a[v4 * 4 + 3], qk, (ull)cB.y);
        }
    }

    float sa, sb;
    unpack2(s01, sa, sb);
    const ull inv = pack2(1.f / sa, 1.f / sb);

    float* po = out + base + n;
    #pragma unroll
    for (int v = 0; v < 16; v++) {
        ull r = mul2(a[v], inv);
        float r0, r1;
        unpack2(r, r0, r1);
        *(float2*)(po + (size_t)v * NN) = make_float2(r0, r1);
    }
}

// ---------------------------------------------------------------------------
extern "C" void kernel_launch(void* const* d_in, const int* in_sizes, int n_in,
                              void* d_out, int out_size) {
    const float* x1 = (const float*)d_in[0];   // values
    const float* x2 = (const float*)d_in[1];   // keys/queries
    float* out = (float*)d_out;

    cudaFuncSetAttribute(ctx_kernel,
                         cudaFuncAttributeMaxDynamicSharedMemorySize,
                         (int)CTX_SMEM);

    ctx_kernel<<<dim3(NCHUNK, BHEADS), 256, CTX_SMEM>>>(x1, x2);
    out_kernel<<<dim3(32, BHEADS), 256>>>(x2, out);
}

// round 10
// speedup vs baseline: 1.7200x; 1.7200x over previous
#include <cuda_runtime.h>

// Cross_Attention_32469952757796 — R10 build (R9 resubmit after infra failure):
// ctx = scalar FFMA, TILE2=512 static smem, 3 CTA/SM, depth-1 x2 prefetch;
// out = proven R7 kernel.
#define NN      16384            // H*W
#define BHEADS  64               // B * HEADS
#define TILE2   512              // N-chunk for ctx kernel
#define NCHUNK  (NN / TILE2)     // 32

// Scratch (allocation-free rule: __device__ globals). Fully overwritten each run.
__device__ float g_part[BHEADS][NCHUNK][256];  // per-chunk ctx partials [k*16+v]
__device__ float g_rsp[BHEADS][NCHUNK][16];    // per-chunk rowsum partials

typedef unsigned long long ull;

// ---- packed f32x2 helpers (sm_100a) — used by out_kernel only -------------
__device__ __forceinline__ ull pack2(float lo, float hi) {
    ull d; asm("mov.b64 %0, {%1, %2};" : "=l"(d) : "f"(lo), "f"(hi)); return d;
}
__device__ __forceinline__ void unpack2(ull v, float& a, float& b) {
    asm("mov.b64 {%0, %1}, %2;" : "=f"(a), "=f"(b) : "l"(v));
}
__device__ __forceinline__ void fma2(ull& d, ull a, ull b) {
    asm("fma.rn.f32x2 %0, %1, %2, %0;" : "+l"(d) : "l"(a), "l"(b));
}
__device__ __forceinline__ ull add2(ull a, ull b) {
    ull d; asm("add.rn.f32x2 %0, %1, %2;" : "=l"(d) : "l"(a), "l"(b)); return d;
}
__device__ __forceinline__ ull mul2(ull a, ull b) {
    ull d; asm("mul.rn.f32x2 %0, %1, %2;" : "=l"(d) : "l"(a), "l"(b)); return d;
}

// ---------------------------------------------------------------------------
// Kernel 1: per-chunk unnormalized context + row sums (no atomics):
//   g_part[bh][ch][k][v] = sum_{n in ch} exp(x2[k,n]) * x1[v,n]
//   g_rsp[bh][ch][k]     = sum_{n in ch} exp(x2[k,n])
// grid = (NCHUNK, 64), 256 threads (8 warps). Warp w owns k = 2w, 2w+1.
// 32 KB static smem + <=85 regs -> 3 CTA/SM (24 warps). x2 loads for step
// jt+1 issued before consuming step jt (depth-1 prefetch).
// ---------------------------------------------------------------------------
__global__ __launch_bounds__(256, 3) void ctx_kernel(const float* __restrict__ x1,
                                                     const float* __restrict__ x2) {
    __shared__ float smv[16 * TILE2];   // 32 KB

    const int bh    = blockIdx.y;
    const int chunk = blockIdx.x;
    const int n0    = chunk * TILE2;
    const int tid   = threadIdx.x;

    // cooperative float4 load of x1 tile [16][TILE2]
    const float* vb = x1 + (size_t)bh * 16 * NN + n0;
    #pragma unroll
    for (int rep = 0; rep < 8; rep++) {
        int idx = rep * 256 + tid;
        int c   = idx >> 7;            // / (TILE2/4)
        int j4  = idx & 127;
        ((float4*)smv)[c * (TILE2 / 4) + j4] =
            ((const float4*)(vb + (size_t)c * NN))[j4];
    }
    __syncthreads();

    const int w    = tid >> 5;
    const int lane = tid & 31;
    const int k0   = w * 2;
    const float* q0 = x2 + (size_t)(bh * 16 + k0) * NN + n0 + lane * 4;
    const float* q1 = q0 + NN;

    float acc0[16], acc1[16];
    #pragma unroll
    for (int v = 0; v < 16; v++) { acc0[v] = 0.f; acc1[v] = 0.f; }
    float s0 = 0.f, s1 = 0.f;

    // depth-1 prefetch pipeline over 4 steps of 128 columns
    float4 a = *(const float4*)(q0);
    float4 b = *(const float4*)(q1);
    #pragma unroll
    for (int jt = 0; jt < 4; jt++) {
        float4 an, bn;
        if (jt < 3) {
            an = *(const float4*)(q0 + (jt + 1) * 128);
            bn = *(const float4*)(q1 + (jt + 1) * 128);
        }
        const float p0 = __expf(a.x), p1 = __expf(a.y);
        const float p2 = __expf(a.z), p3 = __expf(a.w);
        const float r0 = __expf(b.x), r1 = __expf(b.y);
        const float r2 = __expf(b.z), r3 = __expf(b.w);
        s0 += (p0 + p1) + (p2 + p3);
        s1 += (r0 + r1) + (r2 + r3);

        const int j = jt * 128 + lane * 4;
        #pragma unroll
        for (int v = 0; v < 16; v++) {
            float4 vv = *(const float4*)&smv[v * TILE2 + j];
            acc0[v] += p0 * vv.x + p1 * vv.y + p2 * vv.z + p3 * vv.w;
            acc1[v] += r0 * vv.x + r1 * vv.y + r2 * vv.z + r3 * vv.w;
        }
        a = an; b = bn;
    }

    // warp butterfly over 34 scalars
    float sc[34];
    #pragma unroll
    for (int v = 0; v < 16; v++) { sc[v] = acc0[v]; sc[16 + v] = acc1[v]; }
    sc[32] = s0; sc[33] = s1;

    #pragma unroll
    for (int off = 16; off > 0; off >>= 1) {
        #pragma unroll
        for (int i = 0; i < 34; i++)
            sc[i] += __shfl_xor_sync(0xffffffffu, sc[i], off);
    }

    if (lane == 0) {
        float* dst = &g_part[bh][chunk][k0 * 16];
        #pragma unroll
        for (int v = 0; v < 16; v++) { dst[v] = sc[v]; dst[16 + v] = sc[16 + v]; }
        g_rsp[bh][chunk][k0]     = sc[32];
        g_rsp[bh][chunk][k0 + 1] = sc[33];
    }
}

// ---------------------------------------------------------------------------
// Kernel 2 (unchanged from R7, 35.9us): out[v,n] =
//   sum_k (ctx[k,v]/S_k) * softmax_k(x2[:,n])[k]
// grid = (32, 64), 256 threads; each thread owns ONE float2 column pair.
// ctx staged as duplicated {c,c} ull pairs; one LDS.128 broadcast per 2 fma2.
// ---------------------------------------------------------------------------
__global__ __launch_bounds__(256, 4) void out_kernel(const float* __restrict__ x2,
                                                     float* __restrict__ out) {
    __shared__ ull   sctx2[256];   // [k][v], each = {c,c}
    __shared__ float srs[16];

    const int bh  = blockIdx.y;
    const int tid = threadIdx.x;

    if (tid < 16) {
        float s = 0.f;
        #pragma unroll
        for (int ch = 0; ch < NCHUNK; ch++) s += g_rsp[bh][ch][tid];
        srs[tid] = 1.f / s;
    }
    float cv = 0.f;
    #pragma unroll
    for (int ch = 0; ch < NCHUNK; ch++) cv += g_part[bh][ch][tid];
    __syncthreads();
    {
        const int k = tid >> 4;
        const float c = cv * srs[k];
        sctx2[tid] = pack2(c, c);
    }
    __syncthreads();

    const size_t base = (size_t)bh * 16 * NN;
    const int n = blockIdx.x * 512 + tid * 2;
    const float* px = x2 + base + n;

    ull q[16];
    ull s01 = 0ull;
    #pragma unroll
    for (int k = 0; k < 16; k++) {
        float2 t = *(const float2*)(px + (size_t)k * NN);
        q[k] = pack2(__expf(t.x), __expf(t.y));
        s01 = add2(s01, q[k]);
    }
    float sa, sb;
    unpack2(s01, sa, sb);
    const ull inv = pack2(1.f / sa, 1.f / sb);

    float* po = out + base + n;
    #pragma unroll
    for (int v = 0; v < 16; v += 2) {
        ull a0 = 0ull, a1 = 0ull;
        #pragma unroll
        for (int k = 0; k < 16; k++) {
            // one LDS.128 broadcast -> two fma2
            longlong2 c = *(const longlong2*)&sctx2[k * 16 + v];
            fma2(a0, q[k], (ull)c.x);
            fma2(a1, q[k], (ull)c.y);
        }
        a0 = mul2(a0, inv);
        a1 = mul2(a1, inv);
        float r0, r1, r2, r3;
        unpack2(a0, r0, r1);
        unpack2(a1, r2, r3);
        *(float2*)(po + (size_t)v * NN)       = make_float2(r0, r1);
        *(float2*)(po + (size_t)(v + 1) * NN) = make_float2(r2, r3);
    }
}

// ---------------------------------------------------------------------------
extern "C" void kernel_launch(void* const* d_in, const int* in_sizes, int n_in,
                              void* d_out, int out_size) {
    const float* x1 = (const float*)d_in[0];   // values
    const float* x2 = (const float*)d_in[1];   // keys/queries
    float* out = (float*)d_out;

    ctx_kernel<<<dim3(NCHUNK, BHEADS), 256>>>(x1, x2);
    out_kernel<<<dim3(32, BHEADS), 256>>>(x2, out);
}